// round 4
// baseline (speedup 1.0000x reference)
#include <cuda_runtime.h>
#include <cuda_bf16.h>

// MultiPrototypeLoss — persistent warp-per-row kernel.
// B=16384 rows, C=1000 classes, P=4; 262MB once-read stream (HBM-bound).
// d[b,c] = -logsumexp(-x[b,4c..4c+3]); loss = mean_b (d[b,l]/out_mean)^2.
//
// Warp-per-row: no block barriers in the hot loop; 512B fully-coalesced
// loads per LDG.128 warp-front; reduction = 5 shuffles once per row.
// Labels: runtime int32/int64 detection (JAX x64 ambiguity) — genuine
// little-endian int64 labels in [0,1000) have all odd words zero.

#define NUM_C    1000
#define THREADS  256
#define WARPS    (THREADS / 32)
#define GRID     1024            // 8192 warps -> exactly 2 rows/warp @ B=16384

__device__ double   g_acc   = 0.0;
__device__ unsigned g_count = 0u;

__device__ __forceinline__ float softmin4(float4 v) {
    float m = fminf(fminf(v.x, v.y), fminf(v.z, v.w));
    float s = __expf(m - v.x) + __expf(m - v.y) +
              __expf(m - v.z) + __expf(m - v.w);
    return m - __logf(s);   // = -logsumexp(-v)
}

__global__ __launch_bounds__(THREADS) void mpl_kernel(
    const float4* __restrict__ dist,       // [B, NUM_C] float4 groups
    const int*    __restrict__ labels_raw, // [B] int32 OR int64 (as words)
    float*        __restrict__ out,
    int B)
{
    const int tid = threadIdx.x;
    const int lid = tid & 31;
    const int wid = tid >> 5;

    // --- inline label-dtype detection (1KB broadcast read per block) ---
    int odd_idx = 2 * tid + 1;
    int nz = (odd_idx < B) ? (labels_raw[odd_idx] != 0) : 0;
    const int labels_are_i32 = __syncthreads_or(nz);

    const int gwarp  = blockIdx.x * WARPS + wid;
    const int nwarps = gridDim.x * WARPS;

    double local_acc = 0.0;   // meaningful on lane 0

    for (int row = gwarp; row < B; row += nwarps) {
        const float4* rowp = dist + (size_t)row * NUM_C;
        const int lbl = labels_are_i32 ? labels_raw[row]
                                       : labels_raw[2 * row];
        // this lane owns class indices lid + 32*k, k = 0..31 (k=31 iff lid<8)
        const int klbl = (lbl & 31) == lid ? (lbl >> 5) : -1;

        float sum_d  = 0.0f;
        float in_cls = 0.0f;

#pragma unroll
        for (int ii = 0; ii < 8; ii++) {
            // 4 front-batched LDG.128, 512B coalesced each
            const int c0 = (ii * 4 + 0) * 32 + lid;
            const int c1 = (ii * 4 + 1) * 32 + lid;
            const int c2 = (ii * 4 + 2) * 32 + lid;
            const int c3 = (ii * 4 + 3) * 32 + lid;
            float4 v0 = __ldcs(rowp + c0);
            float4 v1 = __ldcs(rowp + c1);
            float4 v2 = __ldcs(rowp + c2);
            float4 v3;
            const bool has3 = (ii < 7) || (lid < 8);   // c3<1000 iff
            if (has3) v3 = __ldcs(rowp + c3);

            float d0 = softmin4(v0);
            float d1 = softmin4(v1);
            float d2 = softmin4(v2);
            float d3 = has3 ? softmin4(v3) : 0.0f;

            sum_d += (d0 + d1) + (d2 + d3);
            if (klbl == ii * 4 + 0) in_cls = d0;
            if (klbl == ii * 4 + 1) in_cls = d1;
            if (klbl == ii * 4 + 2) in_cls = d2;
            if (klbl == ii * 4 + 3) in_cls = d3;
        }

        // warp reduce (in_cls nonzero on exactly one lane)
#pragma unroll
        for (int off = 16; off > 0; off >>= 1) {
            sum_d  += __shfl_xor_sync(0xFFFFFFFFu, sum_d,  off);
            in_cls += __shfl_xor_sync(0xFFFFFFFFu, in_cls, off);
        }

        if (lid == 0) {
            float out_mean = (sum_d - in_cls) * (1.0f / (NUM_C - 1));
            float r = in_cls / out_mean;
            local_acc += (double)(r * r);
        }
    }

    // block reduce of per-warp partials, one atomic per block
    __shared__ double s_acc[WARPS];
    if (lid == 0) s_acc[wid] = local_acc;
    __syncthreads();

    if (tid == 0) {
        double blk = 0.0;
#pragma unroll
        for (int w = 0; w < WARPS; w++) blk += s_acc[w];
        atomicAdd(&g_acc, blk);
        __threadfence();
        unsigned t = atomicAdd(&g_count, 1u);
        if (t == gridDim.x - 1) {          // last block: finalize + reset
            double a = atomicAdd(&g_acc, 0.0);
            *out = (float)(a / (double)B);
            g_acc   = 0.0;                 // restore invariant for replay
            g_count = 0u;
        }
    }
}

extern "C" void kernel_launch(void* const* d_in, const int* in_sizes, int n_in,
                              void* d_out, int out_size) {
    const float4* dist   = (const float4*)d_in[0];
    const int*    labels = (const int*)d_in[1];
    float*        out    = (float*)d_out;
    const int B = in_sizes[1];   // label element count == batch size

    mpl_kernel<<<GRID, THREADS>>>(dist, labels, out, B);
}

// round 5
// speedup vs baseline: 1.0508x; 1.0508x over previous
#include <cuda_runtime.h>
#include <cuda_bf16.h>

// MultiPrototypeLoss — persistent kernel, block-per-ROW-PAIR.
// B=16384 rows, C=1000 classes, P=4; 262MB once-read stream (HBM-bound).
// d[b,c] = -logsumexp(-x[b,4c..4c+3]); loss = mean_b (d[b,l]/out_mean)^2.
//
// R3 (block-per-row) hit 74% DRAM, limited by per-row dependency chain
// (4 loads in flight -> reduce -> 2 barriers). This processes 2 rows per
// iteration: 8 front-batched LDG.128 per thread, half the barrier drains.
// Labels: runtime int32/int64 detection (JAX x64 ambiguity).

#define NUM_C   1000
#define THREADS 256
#define WARPS   (THREADS / 32)
#define GRID    (148 * 8)       // full residency @ 256 thr, 8 blocks/SM

__device__ double   g_acc   = 0.0;
__device__ unsigned g_count = 0u;

__device__ __forceinline__ float softmin4(float4 v) {
    float m = fminf(fminf(v.x, v.y), fminf(v.z, v.w));
    float s = __expf(m - v.x) + __expf(m - v.y) +
              __expf(m - v.z) + __expf(m - v.w);
    return m - __logf(s);   // = -logsumexp(-v)
}

__global__ __launch_bounds__(THREADS) void mpl_kernel(
    const float4* __restrict__ dist,       // [B, NUM_C] float4 groups
    const int*    __restrict__ labels_raw, // [B] int32 OR int64 (as words)
    float*        __restrict__ out,
    int B)
{
    const int tid = threadIdx.x;
    const int lid = tid & 31;
    const int wid = tid >> 5;

    // --- inline label-dtype detection (1KB broadcast read per block) ---
    int odd_idx = 2 * tid + 1;
    int nz = (odd_idx < B) ? (labels_raw[odd_idx] != 0) : 0;
    const int labels_are_i32 = __syncthreads_or(nz);

    __shared__ float s_sumA[WARPS], s_inA[WARPS];
    __shared__ float s_sumB[WARPS], s_inB[WARPS];

    const int c0 = tid;
    const int c1 = tid + THREADS;
    const int c2 = tid + 2 * THREADS;
    const int c3 = tid + 3 * THREADS;
    const bool has3 = (c3 < NUM_C);

    double local_acc = 0.0;    // meaningful on tid 0
    const int npairs = B >> 1;

    for (int pr = blockIdx.x; pr < npairs; pr += gridDim.x) {
        const int rowA = 2 * pr;
        const float4* pA = dist + (size_t)rowA * NUM_C;
        const float4* pB = pA + NUM_C;
        const int lblA = labels_are_i32 ? labels_raw[rowA]
                                        : labels_raw[2 * rowA];
        const int lblB = labels_are_i32 ? labels_raw[rowA + 1]
                                        : labels_raw[2 * rowA + 2];

        // 8 front-batched independent LDG.128
        float4 a0 = __ldcs(pA + c0);
        float4 a1 = __ldcs(pA + c1);
        float4 a2 = __ldcs(pA + c2);
        float4 b0 = __ldcs(pB + c0);
        float4 b1 = __ldcs(pB + c1);
        float4 b2 = __ldcs(pB + c2);
        float4 a3, b3;
        if (has3) { a3 = __ldcs(pA + c3); b3 = __ldcs(pB + c3); }

        float dA0 = softmin4(a0), dA1 = softmin4(a1), dA2 = softmin4(a2);
        float dB0 = softmin4(b0), dB1 = softmin4(b1), dB2 = softmin4(b2);
        float dA3 = has3 ? softmin4(a3) : 0.0f;
        float dB3 = has3 ? softmin4(b3) : 0.0f;

        float sumA = (dA0 + dA1) + (dA2 + dA3);
        float sumB = (dB0 + dB1) + (dB2 + dB3);
        float inA = 0.0f, inB = 0.0f;
        if (c0 == lblA) inA = dA0;
        if (c1 == lblA) inA = dA1;
        if (c2 == lblA) inA = dA2;
        if (c3 == lblA) inA = dA3;
        if (c0 == lblB) inB = dB0;
        if (c1 == lblB) inB = dB1;
        if (c2 == lblB) inB = dB2;
        if (c3 == lblB) inB = dB3;

#pragma unroll
        for (int off = 16; off > 0; off >>= 1) {
            sumA += __shfl_xor_sync(0xFFFFFFFFu, sumA, off);
            inA  += __shfl_xor_sync(0xFFFFFFFFu, inA,  off);
            sumB += __shfl_xor_sync(0xFFFFFFFFu, sumB, off);
            inB  += __shfl_xor_sync(0xFFFFFFFFu, inB,  off);
        }
        if (lid == 0) {
            s_sumA[wid] = sumA; s_inA[wid] = inA;
            s_sumB[wid] = sumB; s_inB[wid] = inB;
        }
        __syncthreads();

        if (tid == 0) {
            float tA = 0.f, iA = 0.f, tB = 0.f, iB = 0.f;
#pragma unroll
            for (int w = 0; w < WARPS; w++) {
                tA += s_sumA[w]; iA += s_inA[w];
                tB += s_sumB[w]; iB += s_inB[w];
            }
            float omA = (tA - iA) * (1.0f / (NUM_C - 1));
            float omB = (tB - iB) * (1.0f / (NUM_C - 1));
            float rA = iA / omA;
            float rB = iB / omB;
            local_acc += (double)(rA * rA) + (double)(rB * rB);
        }
        __syncthreads();   // protect smem reuse next pair
    }

    if (tid == 0) {
        atomicAdd(&g_acc, local_acc);
        __threadfence();
        unsigned t = atomicAdd(&g_count, 1u);
        if (t == gridDim.x - 1) {          // last block: finalize + reset
            double a = atomicAdd(&g_acc, 0.0);
            *out = (float)(a / (double)B);
            g_acc   = 0.0;                 // restore invariant for replay
            g_count = 0u;
        }
    }
}

extern "C" void kernel_launch(void* const* d_in, const int* in_sizes, int n_in,
                              void* d_out, int out_size) {
    const float4* dist   = (const float4*)d_in[0];
    const int*    labels = (const int*)d_in[1];
    float*        out    = (float*)d_out;
    const int B = in_sizes[1];   // label element count == batch size

    mpl_kernel<<<GRID, THREADS>>>(dist, labels, out, B);
}